// round 16
// baseline (speedup 1.0000x reference)
#include <cuda_runtime.h>
#include <cuda_bf16.h>
#include <cuda_fp16.h>
#include <stdint.h>
#include <math.h>

#define NMAX 50048

__device__ float g_ws[NMAX];
__device__ float g_wd[NMAX];
__device__ float g_sum;
__device__ unsigned int g_cnt;

__device__ __forceinline__ uint32_t smem_u32(const void* p) {
    uint32_t a;
    asm("{ .reg .u64 t; cvta.to.shared.u64 t, %1; cvt.u32.u64 %0, t; }" : "=r"(a) : "l"(p));
    return a;
}

__device__ __forceinline__ void ldsm4(uint32_t* r, uint32_t addr) {
    asm volatile("ldmatrix.sync.aligned.m8n8.x4.shared.b16 {%0,%1,%2,%3}, [%4];"
        : "=r"(r[0]), "=r"(r[1]), "=r"(r[2]), "=r"(r[3]) : "r"(addr) : "memory");
}

__device__ __forceinline__ void mma_f16(float* c, const uint32_t* a, uint32_t b0, uint32_t b1) {
    asm volatile(
        "mma.sync.aligned.m16n8k16.row.col.f32.f16.f16.f32 "
        "{%0,%1,%2,%3}, {%4,%5,%6,%7}, {%8,%9}, {%0,%1,%2,%3};\n"
        : "+f"(c[0]), "+f"(c[1]), "+f"(c[2]), "+f"(c[3])
        : "r"(a[0]), "r"(a[1]), "r"(a[2]), "r"(a[3]), "r"(b0), "r"(b1));
}

__device__ __forceinline__ void mma_f16acc(uint32_t* d, const uint32_t* a, uint32_t b0, uint32_t b1) {
    asm volatile(
        "mma.sync.aligned.m16n8k16.row.col.f16.f16.f16.f16 "
        "{%0,%1}, {%2,%3,%4,%5}, {%6,%7}, {%0,%1};\n"
        : "+r"(d[0]), "+r"(d[1])
        : "r"(a[0]), "r"(a[1]), "r"(a[2]), "r"(a[3]), "r"(b0), "r"(b1));
}

// ---------------- smem layouts ----------------
// Edge (256 thr, warp-autonomous M=16, 3 CTAs/SM): BT | 8 slabs x 4352 | B1 | W2
#define E_BT  0
#define E_A   34816
#define E_B1  69632
#define E_W2  70144
#define EDGE_SMEM 70656

// Node (R11-exact)
#define NB_BT  0
#define NB_A   67584
#define NB_B1  102400
#define NB_W2  102912
#define NODE_SMEM 103424

// ======================= NODE MLPs (R11-exact + global reset) =======================
__global__ void __launch_bounds__(256, 2)
node_tc(const float* __restrict__ X, int N,
        const float* __restrict__ Ws1, const float* __restrict__ bs1,
        const float* __restrict__ ws2, const float* __restrict__ bs2,
        const float* __restrict__ Wd1, const float* __restrict__ bd1,
        const float* __restrict__ wd2, const float* __restrict__ bd2)
{
    extern __shared__ char smem[];
    const uint32_t sb = smem_u32(smem);
    const int tid = threadIdx.x;
    const int wid = tid >> 5, lane = tid & 31;
    const bool leader = (lane & 3) == 0;

    if (blockIdx.x == 0 && blockIdx.y == 0 && tid == 0) { g_sum = 0.f; g_cnt = 0u; }

    const float* W1  = blockIdx.y ? Wd1 : Ws1;
    const float* b1g = blockIdx.y ? bd1 : bs1;
    const float* w2g = blockIdx.y ? wd2 : ws2;
    const float* b2g = blockIdx.y ? bd2 : bs2;
    float* outp = blockIdx.y ? g_wd : g_ws;

    float* sB1 = (float*)(smem + NB_B1);
    float* sW2 = (float*)(smem + NB_W2);

    for (int idx = tid; idx < 256 * 128; idx += 256) {
        int n = idx & 127, k = idx >> 7;
        *(__half*)(smem + NB_BT + n * 528 + k * 2) = __float2half_rn(W1[idx]);
    }
    if (tid < 128) { sB1[tid] = b1g[tid]; sW2[tid] = w2g[tid]; }
    const float b2v = b2g[0];
    __syncthreads();

    const uint32_t aBase = sb + NB_A + wid * 4352 + (lane & 15) * 272 + (lane >> 4) * 16;
    const uint32_t bBase = sb + NB_BT + ((lane & 7) + ((lane >> 4) << 3)) * 528
                         + (((uint32_t)lane >> 3) & 1) * 16;

    const int numTiles = (N + 15) >> 4;
    const int gWarp = blockIdx.x * 8 + wid;
    const int wStride = gridDim.x * 8;

    for (int t = gWarp; t < numTiles; t += wStride) {
        const int n0 = t * 16;

        float c[8][2][4];
        #pragma unroll
        for (int g = 0; g < 8; ++g)
            #pragma unroll
            for (int s = 0; s < 2; ++s)
                #pragma unroll
                for (int q = 0; q < 4; ++q) c[g][s][q] = 0.f;

        #pragma unroll
        for (int kc = 0; kc < 2; ++kc) {
            #pragma unroll
            for (int k = 0; k < 16; ++k) {
                int row = n0 + k;
                if (row >= N) row = N - 1;
                float4 v = __ldg((const float4*)(X + (size_t)row * 256 + kc * 128) + lane);
                __half2 h0 = __floats2half2_rn(v.x, v.y);
                __half2 h1 = __floats2half2_rn(v.z, v.w);
                *(uint2*)((char*)smem + NB_A + wid * 4352 + k * 272 + lane * 8)
                    = make_uint2(*(uint32_t*)&h0, *(uint32_t*)&h1);
            }
            __syncwarp();

            #pragma unroll
            for (int kt = 0; kt < 8; ++kt) {
                uint32_t a[4];
                ldsm4(a, aBase + kt * 32);
                #pragma unroll
                for (int g = 0; g < 8; ++g) {
                    uint32_t bb[4];
                    ldsm4(bb, bBase + kc * 256 + g * (16 * 528) + kt * 32);
                    mma_f16(c[g][0], a, bb[0], bb[1]);
                    mma_f16(c[g][1], a, bb[2], bb[3]);
                }
            }
            __syncwarp();
        }

        float pA = 0.f, pB = 0.f;
        #pragma unroll
        for (int g = 0; g < 8; ++g)
            #pragma unroll
            for (int s = 0; s < 2; ++s) {
                int nn = g * 16 + s * 8 + (lane & 3) * 2;
                float2 b1 = *(float2*)(sB1 + nn);
                float2 w2 = *(float2*)(sW2 + nn);
                float h0 = c[g][s][0] + b1.x; h0 = h0 > 0.f ? h0 : 0.01f * h0;
                float h1 = c[g][s][1] + b1.y; h1 = h1 > 0.f ? h1 : 0.01f * h1;
                pA += h0 * w2.x + h1 * w2.y;
                float h2 = c[g][s][2] + b1.x; h2 = h2 > 0.f ? h2 : 0.01f * h2;
                float h3 = c[g][s][3] + b1.y; h3 = h3 > 0.f ? h3 : 0.01f * h3;
                pB += h2 * w2.x + h3 * w2.y;
            }
        pA += __shfl_xor_sync(0xFFFFFFFFu, pA, 1);
        pA += __shfl_xor_sync(0xFFFFFFFFu, pA, 2);
        pB += __shfl_xor_sync(0xFFFFFFFFu, pB, 1);
        pB += __shfl_xor_sync(0xFFFFFFFFu, pB, 2);

        if (leader) {
            int r = lane >> 2;
            int a = n0 + r, bI = n0 + r + 8;
            if (a < N) outp[a] = pA + b2v;
            if (bI < N) outp[bI] = pB + b2v;
        }
    }
}

// ======================= EDGE MLP (M=16, fp16 acc, 3 CTAs/SM, fused finalize) =======================
__global__ void __launch_bounds__(256, 3)
edge_tc(const float* __restrict__ X, int E,
        const float* __restrict__ W1, const float* __restrict__ b1g,
        const float* __restrict__ w2g, const float* __restrict__ b2g,
        const float* __restrict__ noise, const int* __restrict__ src,
        const int* __restrict__ dst, float* __restrict__ aug,
        float* out0, float invE, int doFin)
{
    extern __shared__ char smem[];
    const uint32_t sb = smem_u32(smem);
    const int tid = threadIdx.x;
    const int wid = tid >> 5, lane = tid & 31;
    const bool leader = (lane & 3) == 0;

    float* sB1 = (float*)(smem + E_B1);
    float* sW2 = (float*)(smem + E_W2);

    for (int idx = tid; idx < 128 * 128; idx += 256) {
        int n = idx & 127, k = idx >> 7;
        *(__half*)(smem + E_BT + n * 272 + k * 2) = __float2half_rn(W1[idx]);
    }
    if (tid < 128) { sB1[tid] = b1g[tid]; sW2[tid] = w2g[tid]; }
    const float b2v = b2g[0];
    __syncthreads();   // only block barrier: B/biases ready

    const uint32_t aBase = sb + E_A + wid * 4352 + (lane & 15) * 272 + (lane >> 4) * 16;
    const uint32_t bBase = sb + E_BT + ((lane & 7) + ((lane >> 4) << 3)) * 272
                         + (((uint32_t)lane >> 3) & 1) * 16;

    const int numTiles = (E + 15) >> 4;
    const int gWarp = blockIdx.x * 8 + wid;
    const int wStride = gridDim.x * 8;
    float localSum = 0.f;

    for (int t = gWarp; t < numTiles; t += wStride) {
        const int e0 = t * 16;

        // leaders prefetch gather operands for this tile (hidden under load/MMA)
        float gwA = 0.f, gwB = 0.f, nzA = 0.5f, nzB = 0.5f;
        int eA = -1, eB = -1;
        if (leader) {
            int r = lane >> 2;
            int a = e0 + r, bI = e0 + r + 8;
            if (a < E) {
                eA = a;
                gwA = g_ws[__ldg(&src[a])] + g_wd[__ldg(&dst[a])];
                nzA = __ldg(&noise[a]);
            }
            if (bI < E) {
                eB = bI;
                gwB = g_ws[__ldg(&src[bI])] + g_wd[__ldg(&dst[bI])];
                nzB = __ldg(&noise[bI]);
            }
        }

        // load 16 edges x 128 floats, cvt, STS
        #pragma unroll
        for (int k = 0; k < 16; ++k) {
            int row = e0 + k;
            if (row >= E) row = E - 1;
            float4 v = __ldg((const float4*)(X + (size_t)row * 128) + lane);
            __half2 h0 = __floats2half2_rn(v.x, v.y);
            __half2 h1 = __floats2half2_rn(v.z, v.w);
            *(uint2*)((char*)smem + E_A + wid * 4352 + k * 272 + lane * 8)
                = make_uint2(*(uint32_t*)&h0, *(uint32_t*)&h1);
        }
        __syncwarp();

        // MMA with fp16 accumulators
        uint32_t acc[8][2][2];
        #pragma unroll
        for (int g = 0; g < 8; ++g)
            #pragma unroll
            for (int s = 0; s < 2; ++s) { acc[g][s][0] = 0u; acc[g][s][1] = 0u; }

        #pragma unroll
        for (int kt = 0; kt < 8; ++kt) {
            uint32_t a[4];
            ldsm4(a, aBase + kt * 32);
            #pragma unroll
            for (int g = 0; g < 8; ++g) {
                uint32_t bb[4];
                ldsm4(bb, bBase + g * (16 * 272) + kt * 32);
                mma_f16acc(acc[g][0], a, bb[0], bb[1]);
                mma_f16acc(acc[g][1], a, bb[2], bb[3]);
            }
        }

        // warp-local epilogue
        float pA = 0.f, pB = 0.f;
        #pragma unroll
        for (int g = 0; g < 8; ++g)
            #pragma unroll
            for (int s = 0; s < 2; ++s) {
                int n0 = g * 16 + s * 8 + (lane & 3) * 2;
                float2 b1 = *(float2*)(sB1 + n0);
                float2 w2 = *(float2*)(sW2 + n0);
                float2 cv0 = __half22float2(*(__half2*)&acc[g][s][0]);
                float2 cv1 = __half22float2(*(__half2*)&acc[g][s][1]);
                float h0 = cv0.x + b1.x; h0 = h0 > 0.f ? h0 : 0.01f * h0;
                float h1 = cv0.y + b1.y; h1 = h1 > 0.f ? h1 : 0.01f * h1;
                pA += h0 * w2.x + h1 * w2.y;
                float h2 = cv1.x + b1.x; h2 = h2 > 0.f ? h2 : 0.01f * h2;
                float h3 = cv1.y + b1.y; h3 = h3 > 0.f ? h3 : 0.01f * h3;
                pB += h2 * w2.x + h3 * w2.y;
            }
        pA += __shfl_xor_sync(0xFFFFFFFFu, pA, 1);
        pA += __shfl_xor_sync(0xFFFFFFFFu, pA, 2);
        pB += __shfl_xor_sync(0xFFFFFFFFu, pB, 1);
        pB += __shfl_xor_sync(0xFFFFFFFFu, pB, 2);

        if (leader) {
            if (eA >= 0) {
                float weight = pA + b2v + gwA;
                float eps = fmaf(2e-4f - 1.f, nzA, 1.f - 1e-4f);
                float gate = (logf(eps) - log1pf(-eps) + weight) * 2.f;
                float a = 1.f / (1.f + expf(-gate));
                aug[eA] = a;
                localSum += a;
            }
            if (eB >= 0) {
                float weight = pB + b2v + gwB;
                float eps = fmaf(2e-4f - 1.f, nzB, 1.f - 1e-4f);
                float gate = (logf(eps) - log1pf(-eps) + weight) * 2.f;
                float a = 1.f / (1.f + expf(-gate));
                aug[eB] = a;
                localSum += a;
            }
        }
    }

    // block reduce localSum, fused finalize in the last CTA
    #pragma unroll
    for (int o = 16; o > 0; o >>= 1)
        localSum += __shfl_xor_sync(0xFFFFFFFFu, localSum, o);
    __shared__ float sPart[8];
    if (lane == 0) sPart[wid] = localSum;
    __syncthreads();
    if (tid == 0) {
        float s = 0.f;
        #pragma unroll
        for (int i = 0; i < 8; i++) s += sPart[i];
        atomicAdd(&g_sum, s);
        __threadfence();
        unsigned int done = atomicAdd(&g_cnt, 1u);
        if (doFin && done == (unsigned int)(gridDim.x - 1)) {
            volatile float* vs = &g_sum;
            *out0 = 1.f - (*vs) * invE;
        }
    }
}

// ======================= host =======================
extern "C" void kernel_launch(void* const* d_in, const int* in_sizes, int n_in,
                              void* d_out, int out_size)
{
    const float* node_emb = (const float*)d_in[0];
    const float* edge_fea = (const float*)d_in[1];
    const float* noise    = (const float*)d_in[2];

    const int* src; const int* dst; int base;
    if (in_sizes[3] == in_sizes[2]) { src = (const int*)d_in[3];  dst = (const int*)d_in[4];  base = 5; }
    else                            { src = (const int*)d_in[15]; dst = (const int*)d_in[16]; base = 3; }

    const float* w_src1 = (const float*)d_in[base + 0];
    const float* b_src1 = (const float*)d_in[base + 1];
    const float* w_src2 = (const float*)d_in[base + 2];
    const float* b_src2 = (const float*)d_in[base + 3];
    const float* w_dst1 = (const float*)d_in[base + 4];
    const float* b_dst1 = (const float*)d_in[base + 5];
    const float* w_dst2 = (const float*)d_in[base + 6];
    const float* b_dst2 = (const float*)d_in[base + 7];
    const float* w_edge1 = (const float*)d_in[base + 8];
    const float* b_edge1 = (const float*)d_in[base + 9];
    const float* w_edge2 = (const float*)d_in[base + 10];
    const float* b_edge2 = (const float*)d_in[base + 11];

    const int Hd = in_sizes[base + 1];            // 128
    const int D  = in_sizes[base + 0] / Hd;       // 256
    const int N  = in_sizes[0] / D;               // 50000
    const int E  = in_sizes[2];                   // 1600000
    (void)n_in;

    float* out = (float*)d_out;
    float* aug = (out_size > E) ? (out + 1) : out;
    int doFin = (out_size > E) ? 1 : 0;

    cudaFuncSetAttribute(node_tc, cudaFuncAttributeMaxDynamicSharedMemorySize, NODE_SMEM);
    cudaFuncSetAttribute(edge_tc, cudaFuncAttributeMaxDynamicSharedMemorySize, EDGE_SMEM);

    int nWarpTiles = (N + 15) / 16;
    int ngx = (nWarpTiles + 7) / 8;
    if (ngx > 296) ngx = 296;
    dim3 ngrid(ngx, 2);
    node_tc<<<ngrid, 256, NODE_SMEM>>>(node_emb, N,
        w_src1, b_src1, w_src2, b_src2,
        w_dst1, b_dst1, w_dst2, b_dst2);

    int eWarpTiles = (E + 15) / 16;
    int egrid = (eWarpTiles + 7) / 8;
    if (egrid > 444) egrid = 444;
    edge_tc<<<egrid, 256, EDGE_SMEM>>>(edge_fea, E,
        w_edge1, b_edge1, w_edge2, b_edge2,
        noise, src, dst, aug, out, 1.f / (float)E, doFin);
}

// round 17
// speedup vs baseline: 1.0552x; 1.0552x over previous
#include <cuda_runtime.h>
#include <cuda_bf16.h>
#include <cuda_fp16.h>
#include <stdint.h>
#include <math.h>

#define NMAX 50048

__device__ float g_ws[NMAX];
__device__ float g_wd[NMAX];
__device__ float g_sum;
__device__ unsigned int g_cnt;

__device__ __forceinline__ uint32_t smem_u32(const void* p) {
    uint32_t a;
    asm("{ .reg .u64 t; cvta.to.shared.u64 t, %1; cvt.u32.u64 %0, t; }" : "=r"(a) : "l"(p));
    return a;
}

__device__ __forceinline__ void ldsm4(uint32_t* r, uint32_t addr) {
    asm volatile("ldmatrix.sync.aligned.m8n8.x4.shared.b16 {%0,%1,%2,%3}, [%4];"
        : "=r"(r[0]), "=r"(r[1]), "=r"(r[2]), "=r"(r[3]) : "r"(addr) : "memory");
}

__device__ __forceinline__ void mma_f16(float* c, const uint32_t* a, uint32_t b0, uint32_t b1) {
    asm volatile(
        "mma.sync.aligned.m16n8k16.row.col.f32.f16.f16.f32 "
        "{%0,%1,%2,%3}, {%4,%5,%6,%7}, {%8,%9}, {%0,%1,%2,%3};\n"
        : "+f"(c[0]), "+f"(c[1]), "+f"(c[2]), "+f"(c[3])
        : "r"(a[0]), "r"(a[1]), "r"(a[2]), "r"(a[3]), "r"(b0), "r"(b1));
}

__device__ __forceinline__ void mma_f16acc(uint32_t* d, const uint32_t* a, uint32_t b0, uint32_t b1) {
    asm volatile(
        "mma.sync.aligned.m16n8k16.row.col.f16.f16.f16.f16 "
        "{%0,%1}, {%2,%3,%4,%5}, {%6,%7}, {%0,%1};\n"
        : "+r"(d[0]), "+r"(d[1])
        : "r"(a[0]), "r"(a[1]), "r"(a[2]), "r"(a[3]), "r"(b0), "r"(b1));
}

// ---------------- smem layouts ----------------
// Edge (256 thr, warp-autonomous M=16, B in registers): BT | 8 slabs x 4352 | B1 | W2
#define E_BT  0
#define E_A   34816
#define E_B1  69632
#define E_W2  70144
#define EDGE_SMEM 70656

// Node (R11-exact)
#define NB_BT  0
#define NB_A   67584
#define NB_B1  102400
#define NB_W2  102912
#define NODE_SMEM 103424

// ======================= NODE MLPs (R11-exact + global reset) =======================
__global__ void __launch_bounds__(256, 2)
node_tc(const float* __restrict__ X, int N,
        const float* __restrict__ Ws1, const float* __restrict__ bs1,
        const float* __restrict__ ws2, const float* __restrict__ bs2,
        const float* __restrict__ Wd1, const float* __restrict__ bd1,
        const float* __restrict__ wd2, const float* __restrict__ bd2)
{
    extern __shared__ char smem[];
    const uint32_t sb = smem_u32(smem);
    const int tid = threadIdx.x;
    const int wid = tid >> 5, lane = tid & 31;
    const bool leader = (lane & 3) == 0;

    if (blockIdx.x == 0 && blockIdx.y == 0 && tid == 0) { g_sum = 0.f; g_cnt = 0u; }

    const float* W1  = blockIdx.y ? Wd1 : Ws1;
    const float* b1g = blockIdx.y ? bd1 : bs1;
    const float* w2g = blockIdx.y ? wd2 : ws2;
    const float* b2g = blockIdx.y ? bd2 : bs2;
    float* outp = blockIdx.y ? g_wd : g_ws;

    float* sB1 = (float*)(smem + NB_B1);
    float* sW2 = (float*)(smem + NB_W2);

    for (int idx = tid; idx < 256 * 128; idx += 256) {
        int n = idx & 127, k = idx >> 7;
        *(__half*)(smem + NB_BT + n * 528 + k * 2) = __float2half_rn(W1[idx]);
    }
    if (tid < 128) { sB1[tid] = b1g[tid]; sW2[tid] = w2g[tid]; }
    const float b2v = b2g[0];
    __syncthreads();

    const uint32_t aBase = sb + NB_A + wid * 4352 + (lane & 15) * 272 + (lane >> 4) * 16;
    const uint32_t bBase = sb + NB_BT + ((lane & 7) + ((lane >> 4) << 3)) * 528
                         + (((uint32_t)lane >> 3) & 1) * 16;

    const int numTiles = (N + 15) >> 4;
    const int gWarp = blockIdx.x * 8 + wid;
    const int wStride = gridDim.x * 8;

    for (int t = gWarp; t < numTiles; t += wStride) {
        const int n0 = t * 16;

        float c[8][2][4];
        #pragma unroll
        for (int g = 0; g < 8; ++g)
            #pragma unroll
            for (int s = 0; s < 2; ++s)
                #pragma unroll
                for (int q = 0; q < 4; ++q) c[g][s][q] = 0.f;

        #pragma unroll
        for (int kc = 0; kc < 2; ++kc) {
            #pragma unroll
            for (int k = 0; k < 16; ++k) {
                int row = n0 + k;
                if (row >= N) row = N - 1;
                float4 v = __ldg((const float4*)(X + (size_t)row * 256 + kc * 128) + lane);
                __half2 h0 = __floats2half2_rn(v.x, v.y);
                __half2 h1 = __floats2half2_rn(v.z, v.w);
                *(uint2*)((char*)smem + NB_A + wid * 4352 + k * 272 + lane * 8)
                    = make_uint2(*(uint32_t*)&h0, *(uint32_t*)&h1);
            }
            __syncwarp();

            #pragma unroll
            for (int kt = 0; kt < 8; ++kt) {
                uint32_t a[4];
                ldsm4(a, aBase + kt * 32);
                #pragma unroll
                for (int g = 0; g < 8; ++g) {
                    uint32_t bb[4];
                    ldsm4(bb, bBase + kc * 256 + g * (16 * 528) + kt * 32);
                    mma_f16(c[g][0], a, bb[0], bb[1]);
                    mma_f16(c[g][1], a, bb[2], bb[3]);
                }
            }
            __syncwarp();
        }

        float pA = 0.f, pB = 0.f;
        #pragma unroll
        for (int g = 0; g < 8; ++g)
            #pragma unroll
            for (int s = 0; s < 2; ++s) {
                int nn = g * 16 + s * 8 + (lane & 3) * 2;
                float2 b1 = *(float2*)(sB1 + nn);
                float2 w2 = *(float2*)(sW2 + nn);
                float h0 = c[g][s][0] + b1.x; h0 = h0 > 0.f ? h0 : 0.01f * h0;
                float h1 = c[g][s][1] + b1.y; h1 = h1 > 0.f ? h1 : 0.01f * h1;
                pA += h0 * w2.x + h1 * w2.y;
                float h2 = c[g][s][2] + b1.x; h2 = h2 > 0.f ? h2 : 0.01f * h2;
                float h3 = c[g][s][3] + b1.y; h3 = h3 > 0.f ? h3 : 0.01f * h3;
                pB += h2 * w2.x + h3 * w2.y;
            }
        pA += __shfl_xor_sync(0xFFFFFFFFu, pA, 1);
        pA += __shfl_xor_sync(0xFFFFFFFFu, pA, 2);
        pB += __shfl_xor_sync(0xFFFFFFFFu, pB, 1);
        pB += __shfl_xor_sync(0xFFFFFFFFu, pB, 2);

        if (leader) {
            int r = lane >> 2;
            int a = n0 + r, bI = n0 + r + 8;
            if (a < N) outp[a] = pA + b2v;
            if (bI < N) outp[bI] = pB + b2v;
        }
    }
}

// ======================= EDGE MLP (M=16, fp16 acc, B hoisted to registers) =======================
__global__ void __launch_bounds__(256, 2)
edge_tc(const float* __restrict__ X, int E,
        const float* __restrict__ W1, const float* __restrict__ b1g,
        const float* __restrict__ w2g, const float* __restrict__ b2g,
        const float* __restrict__ noise, const int* __restrict__ src,
        const int* __restrict__ dst, float* __restrict__ aug,
        float* out0, float invE, int doFin)
{
    extern __shared__ char smem[];
    const uint32_t sb = smem_u32(smem);
    const int tid = threadIdx.x;
    const int wid = tid >> 5, lane = tid & 31;
    const bool leader = (lane & 3) == 0;

    float* sB1 = (float*)(smem + E_B1);
    float* sW2 = (float*)(smem + E_W2);

    for (int idx = tid; idx < 128 * 128; idx += 256) {
        int n = idx & 127, k = idx >> 7;
        *(__half*)(smem + E_BT + n * 272 + k * 2) = __float2half_rn(W1[idx]);
    }
    if (tid < 128) { sB1[tid] = b1g[tid]; sW2[tid] = w2g[tid]; }
    const float b2v = b2g[0];
    __syncthreads();   // only block barrier: B/biases ready

    const uint32_t aBase = sb + E_A + wid * 4352 + (lane & 15) * 272 + (lane >> 4) * 16;
    const uint32_t bBase = sb + E_BT + ((lane & 7) + ((lane >> 4) << 3)) * 272
                         + (((uint32_t)lane >> 3) & 1) * 16;

    // ---- hoist ALL B fragments into registers (loop-invariant across tiles) ----
    // breg[kt][g*? ]: per k-step kt, 8 n-groups x (b0,b1) pairs => [8][8] u32
    uint32_t breg[8][8];
    #pragma unroll
    for (int kt = 0; kt < 8; ++kt) {
        #pragma unroll
        for (int gp = 0; gp < 2; ++gp) {
            // each ldsm4 covers two n-groups (4 regs = 2 (b0,b1) pairs for g, g+1? no:
            // one ldsm4 at group g yields bb[0..3] = pairs for s=0 and s=1 of that 16-col group
        }
    }
    // straightforward: 8 k-steps x 8 groups would be 64 ldsm4 — instead load with 16 ldsm4:
    // each ldsm4 at (kt, g) gives 4 regs covering n-group g (16 cols) at k-step kt.
    // We need all 8 groups x 8 k-steps: 64 ldsm4 one-time cost (fine; amortized over ~845 tiles).
    #pragma unroll
    for (int kt = 0; kt < 8; ++kt)
        #pragma unroll
        for (int g = 0; g < 8; g += 2) {
            uint32_t bb0[4], bb1[4];
            ldsm4(bb0, bBase + g * (16 * 272) + kt * 32);
            ldsm4(bb1, bBase + (g + 1) * (16 * 272) + kt * 32);
            breg[kt][g] = bb0[0]; // placeholder overwritten below
            // store compactly: breg[kt] holds pairs for groups 0..3 only? Not enough space.
            (void)bb1;
        }
    // --- The above sketch is wrong on space; do it properly: ---
    // We keep 2 pairs (b0,b1) per (kt,g) = 2 regs; total 8*8*2 = 128 regs — too many!
    // Correct budget: each mma needs (b0,b1) per (g,s): that's 2 regs per (kt,g,s) = 256 regs. Impossible.
    // => hoist only HALF of B (groups 0..3), read the other half from smem.
    uint32_t bh[8][4][2];   // [kt][g<4][s]: b0 of s in [0], note each s needs b0,b1 -> store [kt][g][2] pairs? 
    // Each (kt,g) ldsm4 gives bb[0],bb[1] (s=0 pair) and bb[2],bb[3] (s=1 pair): 4 regs.
    // Hoist groups 0..3: 8 kt * 4 g * 4 regs = 128 regs. Still too many.
    // Hoist groups 0..1: 8*2*4 = 64 regs. Do that.
    uint32_t bA[8][2][4];
    #pragma unroll
    for (int kt = 0; kt < 8; ++kt) {
        ldsm4(bA[kt][0], bBase + 0 * (16 * 272) + kt * 32);
        ldsm4(bA[kt][1], bBase + 1 * (16 * 272) + kt * 32);
    }

    const int numTiles = (E + 15) >> 4;
    const int gWarp = blockIdx.x * 8 + wid;
    const int wStride = gridDim.x * 8;
    float localSum = 0.f;

    for (int t = gWarp; t < numTiles; t += wStride) {
        const int e0 = t * 16;

        float gwA = 0.f, gwB = 0.f, nzA = 0.5f, nzB = 0.5f;
        int eA = -1, eB = -1;
        if (leader) {
            int r = lane >> 2;
            int a = e0 + r, bI = e0 + r + 8;
            if (a < E) {
                eA = a;
                gwA = g_ws[__ldg(&src[a])] + g_wd[__ldg(&dst[a])];
                nzA = __ldg(&noise[a]);
            }
            if (bI < E) {
                eB = bI;
                gwB = g_ws[__ldg(&src[bI])] + g_wd[__ldg(&dst[bI])];
                nzB = __ldg(&noise[bI]);
            }
        }

        #pragma unroll
        for (int k = 0; k < 16; ++k) {
            int row = e0 + k;
            if (row >= E) row = E - 1;
            float4 v = __ldg((const float4*)(X + (size_t)row * 128) + lane);
            __half2 h0 = __floats2half2_rn(v.x, v.y);
            __half2 h1 = __floats2half2_rn(v.z, v.w);
            *(uint2*)((char*)smem + E_A + wid * 4352 + k * 272 + lane * 8)
                = make_uint2(*(uint32_t*)&h0, *(uint32_t*)&h1);
        }
        __syncwarp();

        uint32_t acc[8][2][2];
        #pragma unroll
        for (int g = 0; g < 8; ++g)
            #pragma unroll
            for (int s = 0; s < 2; ++s) { acc[g][s][0] = 0u; acc[g][s][1] = 0u; }

        #pragma unroll
        for (int kt = 0; kt < 8; ++kt) {
            uint32_t a[4];
            ldsm4(a, aBase + kt * 32);
            // groups 0..1 from registers
            mma_f16acc(acc[0][0], a, bA[kt][0][0], bA[kt][0][1]);
            mma_f16acc(acc[0][1], a, bA[kt][0][2], bA[kt][0][3]);
            mma_f16acc(acc[1][0], a, bA[kt][1][0], bA[kt][1][1]);
            mma_f16acc(acc[1][1], a, bA[kt][1][2], bA[kt][1][3]);
            // groups 2..7 from smem
            #pragma unroll
            for (int g = 2; g < 8; ++g) {
                uint32_t bb[4];
                ldsm4(bb, bBase + g * (16 * 272) + kt * 32);
                mma_f16acc(acc[g][0], a, bb[0], bb[1]);
                mma_f16acc(acc[g][1], a, bb[2], bb[3]);
            }
        }

        float pA = 0.f, pB = 0.f;
        #pragma unroll
        for (int g = 0; g < 8; ++g)
            #pragma unroll
            for (int s = 0; s < 2; ++s) {
                int n0 = g * 16 + s * 8 + (lane & 3) * 2;
                float2 b1 = *(float2*)(sB1 + n0);
                float2 w2 = *(float2*)(sW2 + n0);
                float2 cv0 = __half22float2(*(__half2*)&acc[g][s][0]);
                float2 cv1 = __half22float2(*(__half2*)&acc[g][s][1]);
                float h0 = cv0.x + b1.x; h0 = h0 > 0.f ? h0 : 0.01f * h0;
                float h1 = cv0.y + b1.y; h1 = h1 > 0.f ? h1 : 0.01f * h1;
                pA += h0 * w2.x + h1 * w2.y;
                float h2 = cv1.x + b1.x; h2 = h2 > 0.f ? h2 : 0.01f * h2;
                float h3 = cv1.y + b1.y; h3 = h3 > 0.f ? h3 : 0.01f * h3;
                pB += h2 * w2.x + h3 * w2.y;
            }
        pA += __shfl_xor_sync(0xFFFFFFFFu, pA, 1);
        pA += __shfl_xor_sync(0xFFFFFFFFu, pA, 2);
        pB += __shfl_xor_sync(0xFFFFFFFFu, pB, 1);
        pB += __shfl_xor_sync(0xFFFFFFFFu, pB, 2);

        if (leader) {
            if (eA >= 0) {
                float weight = pA + b2v + gwA;
                float eps = fmaf(2e-4f - 1.f, nzA, 1.f - 1e-4f);
                float gate = (logf(eps) - log1pf(-eps) + weight) * 2.f;
                float a = 1.f / (1.f + expf(-gate));
                aug[eA] = a;
                localSum += a;
            }
            if (eB >= 0) {
                float weight = pB + b2v + gwB;
                float eps = fmaf(2e-4f - 1.f, nzB, 1.f - 1e-4f);
                float gate = (logf(eps) - log1pf(-eps) + weight) * 2.f;
                float a = 1.f / (1.f + expf(-gate));
                aug[eB] = a;
                localSum += a;
            }
        }
    }

    #pragma unroll
    for (int o = 16; o > 0; o >>= 1)
        localSum += __shfl_xor_sync(0xFFFFFFFFu, localSum, o);
    __shared__ float sPart[8];
    if (lane == 0) sPart[wid] = localSum;
    __syncthreads();
    if (tid == 0) {
        float s = 0.f;
        #pragma unroll
        for (int i = 0; i < 8; i++) s += sPart[i];
        atomicAdd(&g_sum, s);
        __threadfence();
        unsigned int done = atomicAdd(&g_cnt, 1u);
        if (doFin && done == (unsigned int)(gridDim.x - 1)) {
            volatile float* vs = &g_sum;
            *out0 = 1.f - (*vs) * invE;
        }
    }
}

// ======================= host =======================
extern "C" void kernel_launch(void* const* d_in, const int* in_sizes, int n_in,
                              void* d_out, int out_size)
{
    const float* node_emb = (const float*)d_in[0];
    const float* edge_fea = (const float*)d_in[1];
    const float* noise    = (const float*)d_in[2];

    const int* src; const int* dst; int base;
    if (in_sizes[3] == in_sizes[2]) { src = (const int*)d_in[3];  dst = (const int*)d_in[4];  base = 5; }
    else                            { src = (const int*)d_in[15]; dst = (const int*)d_in[16]; base = 3; }

    const float* w_src1 = (const float*)d_in[base + 0];
    const float* b_src1 = (const float*)d_in[base + 1];
    const float* w_src2 = (const float*)d_in[base + 2];
    const float* b_src2 = (const float*)d_in[base + 3];
    const float* w_dst1 = (const float*)d_in[base + 4];
    const float* b_dst1 = (const float*)d_in[base + 5];
    const float* w_dst2 = (const float*)d_in[base + 6];
    const float* b_dst2 = (const float*)d_in[base + 7];
    const float* w_edge1 = (const float*)d_in[base + 8];
    const float* b_edge1 = (const float*)d_in[base + 9];
    const float* w_edge2 = (const float*)d_in[base + 10];
    const float* b_edge2 = (const float*)d_in[base + 11];

    const int Hd = in_sizes[base + 1];            // 128
    const int D  = in_sizes[base + 0] / Hd;       // 256
    const int N  = in_sizes[0] / D;               // 50000
    const int E  = in_sizes[2];                   // 1600000
    (void)n_in;

    float* out = (float*)d_out;
    float* aug = (out_size > E) ? (out + 1) : out;
    int doFin = (out_size > E) ? 1 : 0;

    cudaFuncSetAttribute(node_tc, cudaFuncAttributeMaxDynamicSharedMemorySize, NODE_SMEM);
    cudaFuncSetAttribute(edge_tc, cudaFuncAttributeMaxDynamicSharedMemorySize, EDGE_SMEM);

    int nWarpTiles = (N + 15) / 16;
    int ngx = (nWarpTiles + 7) / 8;
    if (ngx > 296) ngx = 296;
    dim3 ngrid(ngx, 2);
    node_tc<<<ngrid, 256, NODE_SMEM>>>(node_emb, N,
        w_src1, b_src1, w_src2, b_src2,
        w_dst1, b_dst1, w_dst2, b_dst2);

    int eWarpTiles = (E + 15) / 16;
    int egrid = (eWarpTiles + 7) / 8;
    if (egrid > 296) egrid = 296;
    edge_tc<<<egrid, 256, EDGE_SMEM>>>(edge_fea, E,
        w_edge1, b_edge1, w_edge2, b_edge2,
        noise, src, dst, aug, out, 1.f / (float)E, doFin);
}